// round 11
// baseline (speedup 1.0000x reference)
#include <cuda_runtime.h>
#include <math.h>

// Problem constants
#define BB 32
#define LL 2880
#define CC 862
#define PREDP 720
#define SEGS 48
#define KK 16
#define NINV 60
#define NOUTV 15
#define CDIMV 359
#define NMM 4

#define CPB 8
#define XROW 2884            // padded smem row stride (floats)
#define CBLKS 108            // ceil(862/8)
#define UNITS (BB * CBLKS)   // 3456
#define NTHR 512             // 384 consumers + 128 loaders
#define NCONS 384

// smem float offsets
#define O_XS0   0
#define O_XS1   23072
#define O_SMW   46144        // 3600: map_w transposed [i*60 + o*4 + m]
#define O_WEFF  49744        // 7680: union{ gate_w^T [d*4+m] (1436) | W_eff [i*128+ch*16+o] }
#define O_SCRC  57424        // 384 : consumer scratch; reused as rowsum[128] in matmul phase
#define O_SCRL  57808        // 128 : loader stats scratch (2 bufs x 64)
#define O_GTS   57936        // 32  : gates [8][4]
#define O_STAT  57968        // 64  : per-buf {mean[8], sd[8], istd[8], pad[8]}
#define O_SMB   58032        // 64  : map_b transposed [o*4+m], zero-padded
#define SMEM_FLOATS 58096    // 232,384 bytes

// named barrier ids
#define BFULL0  1            // +buf  (512)
#define BEMPTY0 3            // +buf  (512)
#define BLSYNC  5            // loader-internal (128)
#define BCSYNC  6            // consumer-internal (384)

__device__ __forceinline__ void bar_sync(int id, int cnt) {
    asm volatile("bar.sync %0, %1;" :: "r"(id), "r"(cnt) : "memory");
}
__device__ __forceinline__ void bar_arrive(int id, int cnt) {
    asm volatile("bar.arrive %0, %1;" :: "r"(id), "r"(cnt) : "memory");
}

__global__ __launch_bounds__(NTHR, 1)
void fused_model_kernel(const float* __restrict__ x,
                        const float* __restrict__ conv_w,
                        const float* __restrict__ conv_b,
                        const float* __restrict__ gate_w,
                        const float* __restrict__ gate_b,
                        const float* __restrict__ map_w,
                        const float* __restrict__ map_b,
                        float* __restrict__ out,
                        int gridn)
{
    extern __shared__ float sm[];
    float* smw   = sm + O_SMW;
    float* gwu   = sm + O_WEFF;   // gate_w^T view (conv phase)
    float* weff  = sm + O_WEFF;   // W_eff view (matmul phase)
    float* scrC  = sm + O_SCRC;
    float* rwsum = sm + O_SCRC;   // time-shared with scrC
    float* scrL  = sm + O_SCRL;
    float* gts   = sm + O_GTS;
    float* statv = sm + O_STAT;
    float* smb   = sm + O_SMB;

    const int t   = threadIdx.x;
    const int bid = blockIdx.x;
    const int nu  = (bid < UNITS) ? ((UNITS - 1 - bid) / gridn + 1) : 0;

    // ---- one-time staging (all 512 threads) ----
    for (int q = t; q < 900; q += NTHR) {
        int m = q / 225, r = q % 225;
        int o_ = r / 15, i4 = (r % 15) * 4;
        float4 v = *(const float4*)(map_w + m * 900 + o_ * 60 + i4);
        smw[(i4 + 0) * 60 + o_ * 4 + m] = v.x;
        smw[(i4 + 1) * 60 + o_ * 4 + m] = v.y;
        smw[(i4 + 2) * 60 + o_ * 4 + m] = v.z;
        smw[(i4 + 3) * 60 + o_ * 4 + m] = v.w;
    }
    for (int i = t; i < NMM * CDIMV; i += NTHR) {
        int d = i >> 2, m = i & 3;
        gwu[i] = __ldg(gate_w + m * CDIMV + d);
    }
    if (t < 64) {
        int o = t >> 2, m = t & 3;
        smb[t] = (o < NOUTV) ? __ldg(map_b + m * NOUTV + o) : 0.f;
    }
    __syncthreads();
    if (nu == 0) return;

    if (t >= NCONS) {
        // ==================== LOADER role (warps 12-15, 128 threads) =========
        const int tl   = t - NCONS;
        const int pr   = tl & 3;            // channel pair 0..3
        const int lane = tl >> 2;           // 0..31
        const int w    = tl >> 5;           // loader warp 0..3

        for (int k = 0; k < nu + 2; k++) {
            const int buf = k & 1;
            float* xb = sm + (buf ? O_XS1 : O_XS0);

            // write out unit k-2's staged results, then reuse the buffer
            if (k >= 2) {
                bar_sync(BEMPTY0 + buf, NTHR);
                const int uo  = bid + (k - 2) * gridn;
                const int bo  = uo / CBLKS;
                const int co0 = (uo % CBLKS) * CPB;
                const size_t obase = (size_t)bo * PREDP * CC + co0;
                for (int idx = tl; idx < 4 * PREDP; idx += 128) {
                    int pr2 = idx & 3, p = idx >> 2;
                    int c = co0 + pr2 * 2;
                    float2 v;
                    v.x = xb[(pr2 * 2) * XROW + p];
                    v.y = xb[(pr2 * 2 + 1) * XROW + p];
                    if (c + 1 < CC)
                        *(float2*)(out + obase + (size_t)p * CC + pr2 * 2) = v;
                    else if (c < CC)
                        out[obase + (size_t)p * CC + pr2 * 2] = v.x;
                }
                bar_sync(BLSYNC, 128);   // writeout reads done before gather overwrites
            }
            if (k >= nu) continue;        // tail iterations: writeout only

            const int u = bid + k * gridn;
            const int b = u / CBLKS;
            const int c = (u % CBLKS) * CPB + pr * 2;
            const bool v0 = (c < CC), v1 = (c + 1 < CC);
            const float* gp = x + (size_t)b * LL * CC + c;
            float* r0 = xb + (pr * 2) * XROW;
            float* r1 = r0 + XROW;
            float s0 = 0.f, q0 = 0.f, s1 = 0.f, q1 = 0.f;
            if (v1) {
                #pragma unroll 6
                for (int l = lane; l < LL; l += 32) {
                    float2 vv = *(const float2*)(gp + (size_t)l * CC);
                    r0[l] = vv.x; r1[l] = vv.y;
                    s0 += vv.x; q0 = fmaf(vv.x, vv.x, q0);
                    s1 += vv.y; q1 = fmaf(vv.y, vv.y, q1);
                }
            } else {
                for (int l = lane; l < LL; l += 32) {
                    float a = v0 ? __ldg(gp + (size_t)l * CC) : 0.f;
                    r0[l] = a; r1[l] = 0.f;
                    s0 += a; q0 = fmaf(a, a, q0);
                }
            }
            #pragma unroll
            for (int off = 4; off <= 16; off <<= 1) {
                s0 += __shfl_xor_sync(0xffffffffu, s0, off);
                s1 += __shfl_xor_sync(0xffffffffu, s1, off);
                q0 += __shfl_xor_sync(0xffffffffu, q0, off);
                q1 += __shfl_xor_sync(0xffffffffu, q1, off);
            }
            if ((tl & 31) < 4) {
                float* p = scrL + buf * 64 + w * 16 + pr * 4;
                p[0] = s0; p[1] = s1; p[2] = q0; p[3] = q1;
            }
            bar_sync(BLSYNC, 128);
            if (tl < 8) {
                int pp = tl >> 1, e = tl & 1;
                float s = 0.f, qq = 0.f;
                #pragma unroll
                for (int ww = 0; ww < 4; ww++) {
                    s  += scrL[buf * 64 + ww * 16 + pp * 4 + e];
                    qq += scrL[buf * 64 + ww * 16 + pp * 4 + 2 + e];
                }
                float mean = s * (1.f / LL);
                float var  = fmaxf(qq * (1.f / LL) - mean * mean, 0.f);
                float sd   = sqrtf(var + 1e-10f);
                float* st = statv + buf * 32;
                st[tl] = mean; st[8 + tl] = sd; st[16 + tl] = 1.f / sd;
            }
            bar_arrive(BFULL0 + buf, NTHR);
        }
    } else {
        // ==================== CONSUMER role (warps 0-11, 384 threads) ========
        const int ch = t & 7;               // conv channel
        const int dl = t >> 3;              // conv d-lane 0..47
        // matmul mapping (t < 256): warp = channel; lane = (og, sg)
        const int mch = t >> 5;             // matmul channel (0..7 for t<256)
        const int og  = (t & 31) >> 3;      // o-group 0..3
        const int sg  = t & 7;              // s-group 0..7 (6 s each)

        for (int k = 0; k < nu; k++) {
            const int u   = bid + k * gridn;
            const int buf = k & 1;
            float* xb = sm + (buf ? O_XS1 : O_XS0);
            const float* st = statv + buf * 32;
            const int c0 = (u % CBLKS) * CPB;

            // restage gate_w^T (region was overwritten by previous unit's W_eff)
            if (k > 0) {
                #pragma unroll
                for (int i2 = t; i2 < NMM * CDIMV; i2 += NCONS) {
                    int d = i2 >> 2, m = i2 & 3;
                    gwu[i2] = __ldg(gate_w + m * CDIMV + d);
                }
            }

            // prefetch conv weights before waiting on FULL
            float4 kA, kB, kC, kD; float cb;
            {
                int c = c0 + ch;
                if (c < CC) {
                    const float4* cwp = (const float4*)(conv_w + c * KK);
                    kA = cwp[0]; kB = cwp[1]; kC = cwp[2]; kD = cwp[3];
                    cb = __ldg(conv_b + c);
                } else {
                    kA = make_float4(0.f,0.f,0.f,0.f);
                    kB = kA; kC = kA; kD = kA; cb = 0.f;
                }
            }
            bar_sync(BFULL0 + buf, NTHR);

            // ---- depthwise conv on RAW x (normalize folded) + gate partials ----
            {
                const float ksum = kA.x+kA.y+kA.z+kA.w + kB.x+kB.y+kB.z+kB.w
                                 + kC.x+kC.y+kC.z+kC.w + kD.x+kD.y+kD.z+kD.w;
                const float scale  = st[16 + ch];
                const float offset = cb - st[ch] * ksum * scale;
                const float* row = xb + ch * XROW;
                const int d0 = dl * 8;
                const int dend = (d0 + 8 < CDIMV) ? d0 + 8 : CDIMV;
                float a0 = 0.f, a1 = 0.f, a2 = 0.f, a3 = 0.f;
                if (d0 < dend) {
                    const float4* base = (const float4*)(row + 8 * d0);
                    float4 w0 = base[0], w1 = base[1], w2 = base[2], w3 = base[3];
                    for (int d = d0; d < dend; d++) {
                        float dot = 0.f;
                        dot = fmaf(w0.x, kA.x, dot); dot = fmaf(w0.y, kA.y, dot);
                        dot = fmaf(w0.z, kA.z, dot); dot = fmaf(w0.w, kA.w, dot);
                        dot = fmaf(w1.x, kB.x, dot); dot = fmaf(w1.y, kB.y, dot);
                        dot = fmaf(w1.z, kB.z, dot); dot = fmaf(w1.w, kB.w, dot);
                        dot = fmaf(w2.x, kC.x, dot); dot = fmaf(w2.y, kC.y, dot);
                        dot = fmaf(w2.z, kC.z, dot); dot = fmaf(w2.w, kC.w, dot);
                        dot = fmaf(w3.x, kD.x, dot); dot = fmaf(w3.y, kD.y, dot);
                        dot = fmaf(w3.z, kD.z, dot); dot = fmaf(w3.w, kD.w, dot);
                        float cv = fmaf(dot, scale, offset);
                        int j = d - d0;
                        if (d + 1 < dend) {
                            w0 = w2; w1 = w3;
                            w2 = base[2 * j + 4];
                            w3 = base[2 * j + 5];
                        }
                        float4 gv = *(const float4*)(gwu + d * 4);
                        a0 = fmaf(cv, gv.x, a0);
                        a1 = fmaf(cv, gv.y, a1);
                        a2 = fmaf(cv, gv.z, a2);
                        a3 = fmaf(cv, gv.w, a3);
                    }
                }
                a0 += __shfl_xor_sync(0xffffffffu, a0, 8);
                a0 += __shfl_xor_sync(0xffffffffu, a0, 16);
                a1 += __shfl_xor_sync(0xffffffffu, a1, 8);
                a1 += __shfl_xor_sync(0xffffffffu, a1, 16);
                a2 += __shfl_xor_sync(0xffffffffu, a2, 8);
                a2 += __shfl_xor_sync(0xffffffffu, a2, 16);
                a3 += __shfl_xor_sync(0xffffffffu, a3, 8);
                a3 += __shfl_xor_sync(0xffffffffu, a3, 16);
                if ((t & 31) < 8) {
                    int w = t >> 5;
                    float* p = scrC + w * 32 + ch * 4;
                    p[0] = a0; p[1] = a1; p[2] = a2; p[3] = a3;
                }
            }
            bar_sync(BCSYNC, NCONS);
            if (t < 32) {
                int cc = t >> 2, m = t & 3;
                float s = 0.f;
                #pragma unroll
                for (int w = 0; w < 12; w++) s += scrC[w * 32 + cc * 4 + m];
                gts[cc * 4 + m] = s + __ldg(gate_b + m);
            }
            __syncwarp();
            if (t < CPB) {
                float g0 = gts[t*4], g1 = gts[t*4+1], g2 = gts[t*4+2], g3 = gts[t*4+3];
                float mx = fmaxf(fmaxf(g0, g1), fmaxf(g2, g3));
                g0 = expf(g0-mx); g1 = expf(g1-mx); g2 = expf(g2-mx); g3 = expf(g3-mx);
                float inv = 1.f / (g0 + g1 + g2 + g3);
                gts[t*4] = g0*inv; gts[t*4+1] = g1*inv;
                gts[t*4+2] = g2*inv; gts[t*4+3] = g3*inv;
            }
            bar_sync(BCSYNC, NCONS);

            // ---- build W_eff [i*128 + ch*16 + o] (overwrites gate_w region) ----
            #pragma unroll
            for (int p = t; p < 7680; p += NCONS) {
                int i = p >> 7, r = p & 127;
                int cc = r >> 4, o = r & 15;
                float v = 0.f;
                if (o < 15) {
                    float4 mw = *(const float4*)(smw + i * 60 + o * 4);
                    float4 g  = *(const float4*)(gts + cc * 4);
                    v = g.x * mw.x + g.y * mw.y + g.z * mw.z + g.w * mw.w;
                }
                weff[p] = v;
            }
            bar_sync(BCSYNC, NCONS);

            // ---- matmul (warps 0-7) + rowsum (warps 8-11) ----
            unsigned long long acc[12];
            if (t < 256) {
                const float* row = xb + mch * XROW + sg * 6;
                const float* wp  = weff + mch * 16 + og * 4;
                #pragma unroll
                for (int s = 0; s < 12; s++) acc[s] = 0ULL;
                #pragma unroll 4
                for (int i = 0; i < NINV; i++) {
                    float4 w4 = *(const float4*)(wp + i * 128);
                    unsigned long long xl0 = *(const unsigned long long*)(row + i * SEGS);
                    unsigned long long xl1 = *(const unsigned long long*)(row + i * SEGS + 2);
                    unsigned long long xl2 = *(const unsigned long long*)(row + i * SEGS + 4);
                    unsigned long long w2;
                    asm("mov.b64 %0, {%1, %1};" : "=l"(w2) : "f"(w4.x));
                    asm("fma.rn.f32x2 %0, %1, %2, %0;" : "+l"(acc[0]) : "l"(w2), "l"(xl0));
                    asm("fma.rn.f32x2 %0, %1, %2, %0;" : "+l"(acc[1]) : "l"(w2), "l"(xl1));
                    asm("fma.rn.f32x2 %0, %1, %2, %0;" : "+l"(acc[2]) : "l"(w2), "l"(xl2));
                    asm("mov.b64 %0, {%1, %1};" : "=l"(w2) : "f"(w4.y));
                    asm("fma.rn.f32x2 %0, %1, %2, %0;" : "+l"(acc[3]) : "l"(w2), "l"(xl0));
                    asm("fma.rn.f32x2 %0, %1, %2, %0;" : "+l"(acc[4]) : "l"(w2), "l"(xl1));
                    asm("fma.rn.f32x2 %0, %1, %2, %0;" : "+l"(acc[5]) : "l"(w2), "l"(xl2));
                    asm("mov.b64 %0, {%1, %1};" : "=l"(w2) : "f"(w4.z));
                    asm("fma.rn.f32x2 %0, %1, %2, %0;" : "+l"(acc[6]) : "l"(w2), "l"(xl0));
                    asm("fma.rn.f32x2 %0, %1, %2, %0;" : "+l"(acc[7]) : "l"(w2), "l"(xl1));
                    asm("fma.rn.f32x2 %0, %1, %2, %0;" : "+l"(acc[8]) : "l"(w2), "l"(xl2));
                    asm("mov.b64 %0, {%1, %1};" : "=l"(w2) : "f"(w4.w));
                    asm("fma.rn.f32x2 %0, %1, %2, %0;" : "+l"(acc[9])  : "l"(w2), "l"(xl0));
                    asm("fma.rn.f32x2 %0, %1, %2, %0;" : "+l"(acc[10]) : "l"(w2), "l"(xl1));
                    asm("fma.rn.f32x2 %0, %1, %2, %0;" : "+l"(acc[11]) : "l"(w2), "l"(xl2));
                }
            } else {
                int idx = t - 256;           // rowsum over i for (cc, o)
                float s = 0.f;
                #pragma unroll 10
                for (int i = 0; i < NINV; i++) s += weff[i * 128 + idx];
                rwsum[idx] = s;
            }
            bar_sync(BCSYNC, NCONS);   // x reads done; rwsum written
            if (t < 256) {
                const float4 g = *(const float4*)(gts + mch * 4);
                const float sd = st[8 + mch], mu = st[mch];
                float* orow = xb + mch * XROW + sg * 6;
                #pragma unroll
                for (int o2 = 0; o2 < 4; o2++) {
                    int o = og * 4 + o2;
                    if (o < NOUTV) {
                        float4 mb4 = *(const float4*)(smb + o * 4);
                        float be = g.x*mb4.x + g.y*mb4.y + g.z*mb4.z + g.w*mb4.w;
                        float bf = be * sd + mu * (1.f - rwsum[mch * 16 + o]);
                        float* op = orow + o * SEGS;
                        #pragma unroll
                        for (int s = 0; s < 3; s++) {
                            float l0, h0;
                            asm("mov.b64 {%0, %1}, %2;"
                                : "=f"(l0), "=f"(h0) : "l"(acc[o2 * 3 + s]));
                            float2 r = make_float2(l0 + bf, h0 + bf);
                            *(float2*)(op + s * 2) = r;
                        }
                    }
                }
            }
            bar_arrive(BEMPTY0 + buf, NTHR);   // loader writes this buffer out
        }
    }
}

extern "C" void kernel_launch(void* const* d_in, const int* in_sizes, int n_in,
                              void* d_out, int out_size)
{
    const float* x      = (const float*)d_in[0];
    const float* conv_w = (const float*)d_in[1];
    const float* conv_b = (const float*)d_in[2];
    const float* gate_w = (const float*)d_in[3];
    const float* gate_b = (const float*)d_in[4];
    const float* map_w  = (const float*)d_in[5];
    const float* map_b  = (const float*)d_in[6];
    float* out = (float*)d_out;

    int dev = 0, nsm = 148;
    cudaGetDevice(&dev);
    cudaDeviceGetAttribute(&nsm, cudaDevAttrMultiProcessorCount, dev);
    if (nsm > UNITS) nsm = UNITS;

    const int smem_bytes = SMEM_FLOATS * (int)sizeof(float);   // 232,384 B
    cudaFuncSetAttribute(fused_model_kernel,
                         cudaFuncAttributeMaxDynamicSharedMemorySize, smem_bytes);

    fused_model_kernel<<<nsm, NTHR, smem_bytes>>>(x, conv_w, conv_b, gate_w,
                                                  gate_b, map_w, map_b, out, nsm);
}

// round 12
// speedup vs baseline: 1.4251x; 1.4251x over previous
#include <cuda_runtime.h>
#include <math.h>

// Problem constants
#define BB 32
#define LL 2880
#define CC 862
#define PREDP 720
#define SEGS 48
#define KK 16
#define NINV 60
#define NOUTV 15
#define CDIMV 359
#define NMM 4

#define CPB 8
#define XROW 2884            // padded smem row stride (floats), %32 == 4
#define CBLKS 108            // ceil(862/8)
#define UNITS (BB * CBLKS)   // 3456
#define NTHR 512             // 256 consumers + 256 loaders

// smem float offsets
#define O_XS0   0
#define O_XS1   23072
#define O_SMW   46144        // 3600: map_w transposed [i*60 + o*4 + m]
#define O_WEFF  49744        // 7680: union{ gate_w[1436] during conv | W_eff [i*128+ch*16+o] }
#define O_SCRC  57424        // 256 : consumer reduction scratch
#define O_SCRL  57680        // 256 : loader stats scratch (2 bufs x 128)
#define O_GTS   57936        // 32  : gates [8][4]
#define O_STAT  57968        // 64  : per-buf {mean[8], sd[8], istd[8], pad[8]}
#define O_SMB   58032        // 64  : map_b transposed [o*4+m], zero-padded
#define SMEM_FLOATS 58096    // 232,384 bytes

// named barrier ids
#define BFULL0  1            // +buf  (512)
#define BEMPTY0 3            // +buf  (512)
#define BLSYNC  5            // loader-internal (256)
#define BCSYNC  6            // consumer-internal (256)

__device__ __forceinline__ void bar_sync(int id, int cnt) {
    asm volatile("bar.sync %0, %1;" :: "r"(id), "r"(cnt) : "memory");
}
__device__ __forceinline__ void bar_arrive(int id, int cnt) {
    asm volatile("bar.arrive %0, %1;" :: "r"(id), "r"(cnt) : "memory");
}

__global__ __launch_bounds__(NTHR, 1)
void fused_model_kernel(const float* __restrict__ x,
                        const float* __restrict__ conv_w,
                        const float* __restrict__ conv_b,
                        const float* __restrict__ gate_w,
                        const float* __restrict__ gate_b,
                        const float* __restrict__ map_w,
                        const float* __restrict__ map_b,
                        float* __restrict__ out,
                        int gridn)
{
    extern __shared__ float sm[];
    float* smw   = sm + O_SMW;
    float* gwu   = sm + O_WEFF;   // gate_w view (conv phase)
    float* weff  = sm + O_WEFF;   // W_eff view (matmul phase)
    float* scrC  = sm + O_SCRC;
    float* scrL  = sm + O_SCRL;
    float* gts   = sm + O_GTS;
    float* statv = sm + O_STAT;
    float* smb   = sm + O_SMB;

    const int t   = threadIdx.x;
    const int bid = blockIdx.x;
    const int nu  = (bid < UNITS) ? ((UNITS - 1 - bid) / gridn + 1) : 0;

    // ---- one-time staging ----
    for (int q = t; q < 900; q += NTHR) {
        int m = q / 225, r = q % 225;
        int o_ = r / 15, i4 = (r % 15) * 4;
        float4 v = *(const float4*)(map_w + m * 900 + o_ * 60 + i4);
        smw[(i4 + 0) * 60 + o_ * 4 + m] = v.x;
        smw[(i4 + 1) * 60 + o_ * 4 + m] = v.y;
        smw[(i4 + 2) * 60 + o_ * 4 + m] = v.z;
        smw[(i4 + 3) * 60 + o_ * 4 + m] = v.w;
    }
    for (int i = t; i < NMM * CDIMV; i += NTHR)
        gwu[i] = __ldg(gate_w + i);
    if (t < 64) {
        int o = t >> 2, m = t & 3;
        smb[t] = (o < NOUTV) ? __ldg(map_b + m * NOUTV + o) : 0.f;
    }
    __syncthreads();
    if (nu == 0) return;

    if (t >= 256) {
        // ==================== LOADER role (warps 8-15) ====================
        const int tl   = t - 256;
        const int pr   = tl & 3;            // channel pair 0..3
        const int lane = tl >> 2;           // 0..63
        const int w    = tl >> 5;           // loader warp 0..7

        for (int k = 0; k < nu + 2; k++) {
            const int buf = k & 1;
            float* xb = sm + (buf ? O_XS1 : O_XS0);

            if (k >= 2) {
                bar_sync(BEMPTY0 + buf, NTHR);   // consumer staged k-2's output in xb
                // ---- write out unit k-2 (coalesced float2 over channel pairs) ----
                const int uo  = bid + (k - 2) * gridn;
                const int bo  = uo / CBLKS;
                const int co0 = (uo % CBLKS) * CPB;
                const size_t obase = (size_t)bo * PREDP * CC + co0;
                for (int idx = tl; idx < 4 * PREDP; idx += 256) {
                    int pr2 = idx & 3, p = idx >> 2;
                    int c = co0 + pr2 * 2;
                    float2 v;
                    v.x = xb[(pr2 * 2) * XROW + p];
                    v.y = xb[(pr2 * 2 + 1) * XROW + p];
                    if (c + 1 < CC)
                        *(float2*)(out + obase + (size_t)p * CC + pr2 * 2) = v;
                    else if (c < CC)
                        out[obase + (size_t)p * CC + pr2 * 2] = v.x;
                }
                bar_sync(BLSYNC, 256);   // writeout reads done before gather overwrites
            }
            if (k >= nu) continue;        // tail: writeout only

            const int u = bid + k * gridn;
            const int b = u / CBLKS;
            const int c = (u % CBLKS) * CPB + pr * 2;
            const bool v0 = (c < CC), v1 = (c + 1 < CC);
            const float* gp = x + (size_t)b * LL * CC + c;
            float* r0 = xb + (pr * 2) * XROW;
            float* r1 = r0 + XROW;
            float s0 = 0.f, q0 = 0.f, s1 = 0.f, q1 = 0.f;
            if (v1) {
                #pragma unroll 5
                for (int l = lane; l < LL; l += 64) {
                    float2 vv = *(const float2*)(gp + (size_t)l * CC);
                    r0[l] = vv.x; r1[l] = vv.y;
                    s0 += vv.x; q0 = fmaf(vv.x, vv.x, q0);
                    s1 += vv.y; q1 = fmaf(vv.y, vv.y, q1);
                }
            } else {
                for (int l = lane; l < LL; l += 64) {
                    float a = v0 ? __ldg(gp + (size_t)l * CC) : 0.f;
                    r0[l] = a; r1[l] = 0.f;
                    s0 += a; q0 = fmaf(a, a, q0);
                }
            }
            #pragma unroll
            for (int off = 4; off <= 16; off <<= 1) {
                s0 += __shfl_xor_sync(0xffffffffu, s0, off);
                s1 += __shfl_xor_sync(0xffffffffu, s1, off);
                q0 += __shfl_xor_sync(0xffffffffu, q0, off);
                q1 += __shfl_xor_sync(0xffffffffu, q1, off);
            }
            if ((tl & 31) < 4) {
                float* p = scrL + buf * 128 + w * 16 + pr * 4;
                p[0] = s0; p[1] = s1; p[2] = q0; p[3] = q1;
            }
            bar_sync(BLSYNC, 256);
            if (tl < 8) {
                int pp = tl >> 1, e = tl & 1;
                float s = 0.f, qq = 0.f;
                #pragma unroll
                for (int ww = 0; ww < 8; ww++) {
                    s  += scrL[buf * 128 + ww * 16 + pp * 4 + e];
                    qq += scrL[buf * 128 + ww * 16 + pp * 4 + 2 + e];
                }
                float mean = s * (1.f / LL);
                float var  = fmaxf(qq * (1.f / LL) - mean * mean, 0.f);
                float sd   = sqrtf(var + 1e-10f);
                float* st = statv + buf * 32;
                st[tl] = mean; st[8 + tl] = sd; st[16 + tl] = 1.f / sd;
            }
            bar_arrive(BFULL0 + buf, NTHR);
        }
    } else {
        // ==================== CONSUMER role (warps 0-7) ====================
        const int ch = t & 7;               // conv channel
        const int dl = t >> 3;              // conv d-lane 0..31
        const int mch = t >> 5;             // matmul channel = warp id
        const int og  = (t & 31) >> 3;      // o-group 0..3
        const int sg  = t & 7;              // s-group 0..7

        for (int k = 0; k < nu; k++) {
            const int u   = bid + k * gridn;
            const int buf = k & 1;
            float* xb = sm + (buf ? O_XS1 : O_XS0);
            const float* st = statv + buf * 32;
            const int c0 = (u % CBLKS) * CPB;

            // restage gate_w (region was overwritten by previous unit's W_eff)
            if (k > 0) {
                #pragma unroll
                for (int i2 = t; i2 < NMM * CDIMV; i2 += 256)
                    gwu[i2] = __ldg(gate_w + i2);
            }

            // prefetch conv weights before waiting on FULL
            float4 kA, kB, kC, kD; float cb;
            {
                int c = c0 + ch;
                if (c < CC) {
                    const float4* cwp = (const float4*)(conv_w + c * KK);
                    kA = cwp[0]; kB = cwp[1]; kC = cwp[2]; kD = cwp[3];
                    cb = __ldg(conv_b + c);
                } else {
                    kA = make_float4(0.f,0.f,0.f,0.f);
                    kB = kA; kC = kA; kD = kA; cb = 0.f;
                }
            }
            bar_sync(BFULL0 + buf, NTHR);

            // ---- depthwise conv on RAW x (normalize folded) + gate partials ----
            {
                const float ksum = kA.x+kA.y+kA.z+kA.w + kB.x+kB.y+kB.z+kB.w
                                 + kC.x+kC.y+kC.z+kC.w + kD.x+kD.y+kD.z+kD.w;
                const float scale  = st[16 + ch];
                const float offset = cb - st[ch] * ksum * scale;
                const float* row = xb + ch * XROW;
                const int d0 = dl * 12;
                const int dend = (d0 + 12 < CDIMV) ? d0 + 12 : CDIMV;
                float a0 = 0.f, a1 = 0.f, a2 = 0.f, a3 = 0.f;
                if (d0 < dend) {
                    const float4* base = (const float4*)(row + 8 * d0);
                    float4 w0 = base[0], w1 = base[1], w2 = base[2], w3 = base[3];
                    for (int d = d0; d < dend; d++) {
                        float dot = 0.f;
                        dot = fmaf(w0.x, kA.x, dot); dot = fmaf(w0.y, kA.y, dot);
                        dot = fmaf(w0.z, kA.z, dot); dot = fmaf(w0.w, kA.w, dot);
                        dot = fmaf(w1.x, kB.x, dot); dot = fmaf(w1.y, kB.y, dot);
                        dot = fmaf(w1.z, kB.z, dot); dot = fmaf(w1.w, kB.w, dot);
                        dot = fmaf(w2.x, kC.x, dot); dot = fmaf(w2.y, kC.y, dot);
                        dot = fmaf(w2.z, kC.z, dot); dot = fmaf(w2.w, kC.w, dot);
                        dot = fmaf(w3.x, kD.x, dot); dot = fmaf(w3.y, kD.y, dot);
                        dot = fmaf(w3.z, kD.z, dot); dot = fmaf(w3.w, kD.w, dot);
                        float cv = fmaf(dot, scale, offset);
                        int j = d - d0;
                        if (d + 1 < dend) {
                            w0 = w2; w1 = w3;
                            w2 = base[2 * j + 4];
                            w3 = base[2 * j + 5];
                        }
                        a0 = fmaf(cv, gwu[d],             a0);
                        a1 = fmaf(cv, gwu[CDIMV + d],     a1);
                        a2 = fmaf(cv, gwu[2 * CDIMV + d], a2);
                        a3 = fmaf(cv, gwu[3 * CDIMV + d], a3);
                    }
                }
                a0 += __shfl_xor_sync(0xffffffffu, a0, 8);
                a0 += __shfl_xor_sync(0xffffffffu, a0, 16);
                a1 += __shfl_xor_sync(0xffffffffu, a1, 8);
                a1 += __shfl_xor_sync(0xffffffffu, a1, 16);
                a2 += __shfl_xor_sync(0xffffffffu, a2, 8);
                a2 += __shfl_xor_sync(0xffffffffu, a2, 16);
                a3 += __shfl_xor_sync(0xffffffffu, a3, 8);
                a3 += __shfl_xor_sync(0xffffffffu, a3, 16);
                if ((t & 31) < 8) {
                    int w = t >> 5;
                    float* p = scrC + w * 32 + ch * 4;
                    p[0] = a0; p[1] = a1; p[2] = a2; p[3] = a3;
                }
            }
            bar_sync(BCSYNC, 256);
            if (t < 32) {
                int cc = t >> 2, m = t & 3;
                float s = 0.f;
                #pragma unroll
                for (int w = 0; w < 8; w++) s += scrC[w * 32 + cc * 4 + m];
                gts[cc * 4 + m] = s + __ldg(gate_b + m);
            }
            __syncwarp();
            if (t < CPB) {
                float g0 = gts[t*4], g1 = gts[t*4+1], g2 = gts[t*4+2], g3 = gts[t*4+3];
                float mx = fmaxf(fmaxf(g0, g1), fmaxf(g2, g3));
                g0 = expf(g0-mx); g1 = expf(g1-mx); g2 = expf(g2-mx); g3 = expf(g3-mx);
                float inv = 1.f / (g0 + g1 + g2 + g3);
                gts[t*4] = g0*inv; gts[t*4+1] = g1*inv;
                gts[t*4+2] = g2*inv; gts[t*4+3] = g3*inv;
            }
            bar_sync(BCSYNC, 256);

            // ---- build W_eff [i*128 + ch*16 + o] (overwrites gate_w region) ----
            #pragma unroll
            for (int p = t; p < 7680; p += 256) {
                int i = p >> 7, r = p & 127;
                int cc = r >> 4, o = r & 15;
                float v = 0.f;
                if (o < 15) {
                    float4 mw = *(const float4*)(smw + i * 60 + o * 4);
                    float4 g  = *(const float4*)(gts + cc * 4);
                    v = g.x * mw.x + g.y * mw.y + g.z * mw.z + g.w * mw.w;
                }
                weff[p] = v;
            }
            bar_sync(BCSYNC, 256);

            // ---- map matmul: warp = channel, lane tile = 4o x 6s ----
            unsigned long long acc[12];
            float4 rw4 = make_float4(0.f, 0.f, 0.f, 0.f);
            {
                const float* row = xb + mch * XROW + sg * 6;
                const float* wp  = weff + mch * 16 + og * 4;
                #pragma unroll
                for (int s = 0; s < 12; s++) acc[s] = 0ULL;
                #pragma unroll 4
                for (int i = 0; i < NINV; i++) {
                    float4 w4 = *(const float4*)(wp + i * 128);
                    rw4.x += w4.x; rw4.y += w4.y; rw4.z += w4.z; rw4.w += w4.w;
                    unsigned long long xl0 = *(const unsigned long long*)(row + i * SEGS);
                    unsigned long long xl1 = *(const unsigned long long*)(row + i * SEGS + 2);
                    unsigned long long xl2 = *(const unsigned long long*)(row + i * SEGS + 4);
                    unsigned long long w2;
                    asm("mov.b64 %0, {%1, %1};" : "=l"(w2) : "f"(w4.x));
                    asm("fma.rn.f32x2 %0, %1, %2, %0;" : "+l"(acc[0]) : "l"(w2), "l"(xl0));
                    asm("fma.rn.f32x2 %0, %1, %2, %0;" : "+l"(acc[1]) : "l"(w2), "l"(xl1));
                    asm("fma.rn.f32x2 %0, %1, %2, %0;" : "+l"(acc[2]) : "l"(w2), "l"(xl2));
                    asm("mov.b64 %0, {%1, %1};" : "=l"(w2) : "f"(w4.y));
                    asm("fma.rn.f32x2 %0, %1, %2, %0;" : "+l"(acc[3]) : "l"(w2), "l"(xl0));
                    asm("fma.rn.f32x2 %0, %1, %2, %0;" : "+l"(acc[4]) : "l"(w2), "l"(xl1));
                    asm("fma.rn.f32x2 %0, %1, %2, %0;" : "+l"(acc[5]) : "l"(w2), "l"(xl2));
                    asm("mov.b64 %0, {%1, %1};" : "=l"(w2) : "f"(w4.z));
                    asm("fma.rn.f32x2 %0, %1, %2, %0;" : "+l"(acc[6]) : "l"(w2), "l"(xl0));
                    asm("fma.rn.f32x2 %0, %1, %2, %0;" : "+l"(acc[7]) : "l"(w2), "l"(xl1));
                    asm("fma.rn.f32x2 %0, %1, %2, %0;" : "+l"(acc[8]) : "l"(w2), "l"(xl2));
                    asm("mov.b64 %0, {%1, %1};" : "=l"(w2) : "f"(w4.w));
                    asm("fma.rn.f32x2 %0, %1, %2, %0;" : "+l"(acc[9])  : "l"(w2), "l"(xl0));
                    asm("fma.rn.f32x2 %0, %1, %2, %0;" : "+l"(acc[10]) : "l"(w2), "l"(xl1));
                    asm("fma.rn.f32x2 %0, %1, %2, %0;" : "+l"(acc[11]) : "l"(w2), "l"(xl2));
                }
            }
            bar_sync(BCSYNC, 256);   // all x reads done before staging overwrites xb
            {
                const float4 g = *(const float4*)(gts + mch * 4);
                const float sd = st[8 + mch], mu = st[mch];
                float* orow = xb + mch * XROW + sg * 6;
                float rwv[4] = {rw4.x, rw4.y, rw4.z, rw4.w};
                #pragma unroll
                for (int o2 = 0; o2 < 4; o2++) {
                    int o = og * 4 + o2;
                    if (o < NOUTV) {
                        float4 mb4 = *(const float4*)(smb + o * 4);
                        float be = g.x*mb4.x + g.y*mb4.y + g.z*mb4.z + g.w*mb4.w;
                        float bf = be * sd + mu * (1.f - rwv[o2]);
                        float* op = orow + o * SEGS;
                        #pragma unroll
                        for (int s = 0; s < 3; s++) {
                            float l0, h0;
                            asm("mov.b64 {%0, %1}, %2;"
                                : "=f"(l0), "=f"(h0) : "l"(acc[o2 * 3 + s]));
                            float2 r = make_float2(l0 + bf, h0 + bf);
                            *(float2*)(op + s * 2) = r;
                        }
                    }
                }
            }
            bar_arrive(BEMPTY0 + buf, NTHR);   // loader will write this buffer out
        }
    }
}

extern "C" void kernel_launch(void* const* d_in, const int* in_sizes, int n_in,
                              void* d_out, int out_size)
{
    const float* x      = (const float*)d_in[0];
    const float* conv_w = (const float*)d_in[1];
    const float* conv_b = (const float*)d_in[2];
    const float* gate_w = (const float*)d_in[3];
    const float* gate_b = (const float*)d_in[4];
    const float* map_w  = (const float*)d_in[5];
    const float* map_b  = (const float*)d_in[6];
    float* out = (float*)d_out;

    int dev = 0, nsm = 148;
    cudaGetDevice(&dev);
    cudaDeviceGetAttribute(&nsm, cudaDevAttrMultiProcessorCount, dev);
    if (nsm > UNITS) nsm = UNITS;

    const int smem_bytes = SMEM_FLOATS * (int)sizeof(float);   // 232,384 B
    cudaFuncSetAttribute(fused_model_kernel,
                         cudaFuncAttributeMaxDynamicSharedMemorySize, smem_bytes);

    fused_model_kernel<<<nsm, NTHR, smem_bytes>>>(x, conv_w, conv_b, gate_w,
                                                  gate_b, map_w, map_b, out, nsm);
}